// round 14
// baseline (speedup 1.0000x reference)
#include <cuda_runtime.h>
#include <cuda_bf16.h>
#include <cuda_fp16.h>
#include <cstdint>

// Problem dims
#define BB   32
#define TT   512
#define II   512
#define HH   1024
#define OO   512
#define MM   (BB*TT)

#define RNN_BLOCKS 64

// ---------------- scratch (static device globals) ---------------------------
__device__ float g_pre[MM * HH];
__device__ float g_logits[MM * OO];
__device__ float g_zfallback[MM * HH];

__device__ __half g_xh[MM * II],    g_xl[MM * II];
__device__ __half g_wihh[HH * II],  g_wihl[HH * II];
__device__ __half g_wouth[OO * HH], g_woutl[OO * HH];
__device__ __half g_zh16[MM * HH],  g_zl16[MM * HH];
__device__ __half g_h0h16[BB * HH];

// per-(block, mw-half) spread flags (128B apart)
__device__ unsigned g_flags[RNN_BLOCKS * 2 * 32];

// ---------------- helpers ----------------------------------------------------
__device__ __forceinline__ void mma16816h(float& d0, float& d1, float& d2, float& d3,
                                          uint32_t a0, uint32_t a1, uint32_t a2, uint32_t a3,
                                          uint32_t b0, uint32_t b1)
{
    asm volatile(
        "mma.sync.aligned.m16n8k16.row.col.f32.f16.f16.f32 "
        "{%0,%1,%2,%3},{%4,%5,%6,%7},{%8,%9},{%0,%1,%2,%3};"
        : "+f"(d0), "+f"(d1), "+f"(d2), "+f"(d3)
        : "r"(a0), "r"(a1), "r"(a2), "r"(a3), "r"(b0), "r"(b1));
}

__device__ __forceinline__ void ldsm4(uint32_t& r0, uint32_t& r1, uint32_t& r2, uint32_t& r3,
                                      uint32_t addr)
{
    asm volatile("ldmatrix.sync.aligned.m8n8.x4.shared.b16 {%0,%1,%2,%3}, [%4];"
                 : "=r"(r0), "=r"(r1), "=r"(r2), "=r"(r3) : "r"(addr));
}

__device__ __forceinline__ uint32_t lds32(uint32_t a) {
    uint32_t v;
    asm volatile("ld.shared.b32 %0, [%1];" : "=r"(v) : "r"(a));
    return v;
}

__device__ __forceinline__ void cpa16(uint32_t s, const void* g) {
    asm volatile("cp.async.cg.shared.global [%0], [%1], 16;" :: "r"(s), "l"(g));
}

__device__ __forceinline__ uint32_t pack_h2(float x, float y) {
    __half2 t = __floats2half2_rn(x, y);
    return *reinterpret_cast<uint32_t*>(&t);
}

__device__ __forceinline__ void flag_store(unsigned* p, unsigned v) {
    asm volatile("st.release.gpu.u32 [%0], %1;" :: "l"(p), "r"(v));
}
__device__ __forceinline__ void flag_wait(const unsigned* p, unsigned target) {
    unsigned v;
    do {
        asm volatile("ld.acquire.gpu.u32 %0, [%1];" : "=r"(v) : "l"(p));
    } while ((int)(v - target) < 0);
}

__device__ __forceinline__ void nbar_sync(int id, int cnt) {
    asm volatile("bar.sync %0, %1;" :: "r"(id), "r"(cnt) : "memory");
}
__device__ __forceinline__ void nbar_arrive(int id, int cnt) {
    asm volatile("bar.arrive %0, %1;" :: "r"(id), "r"(cnt) : "memory");
}

// ---------------- persistent Elman recurrence (fp16 state, dataflow) ---------
#define WBUF   8448                    // per-warp fp16 slice
#define SM_PS  (8 * WBUF)              // 67584
#define PSROW  18
#define PS_KW  (16 * PSROW)
#define PS_HALF (4 * PS_KW)
#define RNN_SMEM (SM_PS + 2 * 2 * PS_HALF * 4)

__global__ __launch_bounds__(256, 1)
void rnn_persistent(const float* __restrict__ pre,
                    const float* __restrict__ W_hh,
                    float* __restrict__ z_out)
{
    extern __shared__ __align__(16) char dsm[];
    const uint32_t sb = (uint32_t)__cvta_generic_to_shared(dsm);

    const int tid  = threadIdx.x;
    const int wid  = tid >> 5;
    const int lane = tid & 31;
    const int grp  = lane >> 2;       // 0..7
    const int tig  = lane & 3;        // 0..3
    const int jc   = blockIdx.x;      // 0..63
    const int kw   = wid & 3;         // k chunk of 256
    const int mw   = wid >> 2;        // b half

    // replay-safe base (all flags equal at launch start)
    const unsigned base = g_flags[blockIdx.x * 64];

    // ---- preload W fragments (fp16) into registers, whole run ----
    uint32_t w0[2][16], w1[2][16];
    #pragma unroll
    for (int nt = 0; nt < 2; nt++) {
        const int jrow = jc * 16 + nt * 8 + grp;
        const float* Wr = W_hh + (size_t)jrow * HH + kw * 256;
        #pragma unroll
        for (int ki = 0; ki < 16; ki++) {
            int k0 = ki * 16 + tig * 2;
            w0[nt][ki] = pack_h2(Wr[k0],     Wr[k0 + 1]);
            w1[nt][ki] = pack_h2(Wr[k0 + 8], Wr[k0 + 9]);
        }
    }

    // warp-private staging buffer
    const uint32_t wb = sb + (uint32_t)wid * WBUF;
    const uint32_t lrow = (lane & 7) + ((lane >> 3) & 1) * 8;
    const uint32_t aoff = lrow * 528 + ((uint32_t)lane >> 4) * 16;

    // producer half-flag this lane polls: 16 producers cover k in [kw*256,+256)
    const int pflag = ((kw * 16 + (lane & 15)) * 2 + mw) * 32;

    // phase-B mapping within the 128-thread half
    const int ltid = tid & 127;
    const int lb   = ltid >> 3;               // local b 0..15
    const int pbB  = mw * 16 + lb;            // global b
    const int pbJ  = (ltid & 7) * 2;          // j pair within chunk

    float* const psum = (float*)(dsm + SM_PS);   // [parity][mw][kw][16][PSROW]

    const int barA = 1 + mw;   // psum-ready
    const int barB = 3 + mw;   // z-done

    for (int t = 0; t < TT; t++) {
        // prefetch pre (phase-B input, independent of h)
        float2 pre2 = *(const float2*)&pre[((size_t)pbB * TT + t) * HH + jc * 16 + pbJ];

        // ---- dataflow wait: this warp's 16 producer half-flags ----
        if (t > 0)
            flag_wait(&g_flags[pflag], base + (unsigned)t);
        __syncwarp();

        // ---- stage own 16-row x 256-k fp16 slice ----
        {
            const __half* sh;
            size_t rstride, off0;
            if (t == 0) {
                sh = g_h0h16;
                rstride = HH;
                off0 = (size_t)(mw * 16) * HH + kw * 256;
            } else {
                sh = g_zh16;
                rstride = (size_t)TT * HH;
                off0 = ((size_t)(mw * 16) * TT + (t - 1)) * HH + kw * 256;
            }
            #pragma unroll
            for (int i = 0; i < 16; i++) {
                int chunk = i * 32 + lane;
                int row   = chunk >> 5;
                int c     = chunk & 31;
                cpa16(wb + row * 528 + c * 16, sh + off0 + (size_t)row * rstride + c * 8);
            }
            asm volatile("cp.async.commit_group;" ::: "memory");
            asm volatile("cp.async.wait_group 0;" ::: "memory");
            __syncwarp();
        }

        // ---- mma over own k=256 (single fp16 term) ----
        float a1[2][4] = {{0,0,0,0},{0,0,0,0}};
        #pragma unroll
        for (int ki = 0; ki < 16; ki++) {
            uint32_t h0r, h1r, h2r, h3r;
            ldsm4(h0r, h1r, h2r, h3r, wb + aoff + ki * 32);
            #pragma unroll
            for (int nt = 0; nt < 2; nt++) {
                mma16816h(a1[nt][0], a1[nt][1], a1[nt][2], a1[nt][3],
                          h0r, h1r, h2r, h3r, w0[nt][ki], w1[nt][ki]);
            }
        }

        // ---- per-warp k-partials to SMEM (parity double-buffered) ----
        {
            float* pb = psum + ((t & 1) * 2 + mw) * PS_HALF + kw * PS_KW;
            #pragma unroll
            for (int nt = 0; nt < 2; nt++) {
                int jj = nt * 8 + tig * 2;
                float* p = pb + grp * PSROW + jj;
                *(float2*)p               = make_float2(a1[nt][0], a1[nt][1]);
                *(float2*)(p + 8 * PSROW) = make_float2(a1[nt][2], a1[nt][3]);
            }
        }
        nbar_sync(barA, 128);   // psum ready within this half

        // ---- phase B (2 elements/thread): reduce 4 kw, tanh, publish ----
        // ONLY 2 stores before the flag (zh16 + z fp32); zl16 is derived
        // later by zsplit (off the critical chain).
        {
            const float* pb = psum + ((t & 1) * 2 + mw) * PS_HALF;
            float s0 = pre2.x, s1 = pre2.y;
            #pragma unroll
            for (int kk = 0; kk < 4; kk++) {
                float2 p = *(float2*)&pb[kk * PS_KW + lb * PSROW + pbJ];
                s0 += p.x; s1 += p.y;
            }
            float h0v = tanhf(s0);
            float h1v = tanhf(s1);
            size_t zidx = ((size_t)pbB * TT + t) * HH + jc * 16 + pbJ;
            *(uint32_t*)&g_zh16[zidx] = pack_h2(h0v, h1v);
            *(float2*)&z_out[zidx]    = make_float2(h0v, h1v);
        }

        // ---- z-done: kw=0 warp syncs + publishes; others arrive & fly ----
        if (kw == 0) {
            nbar_sync(barB, 128);
            if (lane == 0)
                flag_store(&g_flags[(blockIdx.x * 2 + mw) * 32], base + (unsigned)t + 1u);
        } else {
            nbar_arrive(barB, 128);
        }
    }
}

// ---------------- fused prep: fp16-pair splits of x, W_ih, W_out; h0 conv ----
#define N_X   (MM * II)
#define N_WI  (HH * II)
#define N_WO  (OO * HH)
#define N_H0  (BB * HH)
#define N_PREP (N_X + N_WI + N_WO + N_H0)

__global__ __launch_bounds__(256)
void prep_all(const float* __restrict__ x, const float* __restrict__ W_ih,
              const float* __restrict__ W_out, const float* __restrict__ h0)
{
    int stride = gridDim.x * 256;
    for (int i = blockIdx.x * 256 + threadIdx.x; i < N_PREP; i += stride) {
        const float* src;
        __half *hi, *lo;
        int idx = i;
        if (idx < N_X)                    { src = x;     hi = g_xh;    lo = g_xl; }
        else if ((idx -= N_X) < N_WI)     { src = W_ih;  hi = g_wihh;  lo = g_wihl; }
        else if ((idx -= N_WI) < N_WO)    { src = W_out; hi = g_wouth; lo = g_woutl; }
        else { idx -= N_WO;
            g_h0h16[idx] = __float2half_rn(h0[idx]);
            continue;
        }
        float v = src[idx];
        __half h = __float2half_rn(v);
        hi[idx] = h;
        lo[idx] = __float2half_rn(v - __half2float(h));
    }
}

// ---------------- z fp32 -> fp16 hi/lo (recompute; hi is bit-identical) ------
__global__ __launch_bounds__(256)
void zsplit(const float* __restrict__ z)
{
    int i = blockIdx.x * 256 + threadIdx.x;
    if (i < MM * HH) {
        float v = z[i];
        __half h = __float2half_rn(v);
        g_zh16[i] = h;
        g_zl16[i] = __float2half_rn(v - __half2float(h));
    }
}

// ---------------- mma.sync fp16-pair 3-term GEMM (2 CTAs/SM) -----------------
#define GT_BYTES  (128 * 80)
#define GBUF      (4 * GT_BYTES)
#define GSMEM     (2 * GBUF)

__global__ __launch_bounds__(256, 2)
void hgemm(int M, int N, int K,
           const __half* __restrict__ Ah, const __half* __restrict__ Al,
           const __half* __restrict__ Bh, const __half* __restrict__ Bl,
           const float* __restrict__ bias1, const float* __restrict__ bias2,
           float* __restrict__ C)
{
    extern __shared__ __align__(16) char dsm[];
    const uint32_t sb = (uint32_t)__cvta_generic_to_shared(dsm);

    const int tid  = threadIdx.x;
    const int wid  = tid >> 5;
    const int lane = tid & 31;
    const int grp  = lane >> 2;
    const int tig  = lane & 3;
    const int wm   = wid & 1;
    const int wn   = wid >> 1;
    const int m0   = blockIdx.x * 128;
    const int n0   = blockIdx.y * 128;

    float acc[4][4][4];
    #pragma unroll
    for (int i = 0; i < 4; i++)
        #pragma unroll
        for (int j = 0; j < 4; j++)
            #pragma unroll
            for (int q = 0; q < 4; q++) acc[i][j][q] = 0.f;

    const int lrow = tid >> 2;
    const int lc16 = tid & 3;

    auto issue = [&](int kt, int buf) {
        #pragma unroll
        for (int r = 0; r < 2; r++) {
            int row = lrow + r * 64;
            uint32_t so = (uint32_t)buf * GBUF + row * 80 + lc16 * 16;
            size_t goA = (size_t)(m0 + row) * K + kt * 32 + lc16 * 8;
            size_t goB = (size_t)(n0 + row) * K + kt * 32 + lc16 * 8;
            cpa16(sb + so,                Ah + goA);
            cpa16(sb + so + GT_BYTES,     Al + goA);
            cpa16(sb + so + 2 * GT_BYTES, Bh + goB);
            cpa16(sb + so + 3 * GT_BYTES, Bl + goB);
        }
        asm volatile("cp.async.commit_group;" ::: "memory");
    };

    const int KT = K >> 5;
    issue(0, 0);

    for (int kt = 0; kt < KT; kt++) {
        if (kt + 1 < KT) {
            issue(kt + 1, (kt + 1) & 1);
            asm volatile("cp.async.wait_group 1;" ::: "memory");
        } else {
            asm volatile("cp.async.wait_group 0;" ::: "memory");
        }
        __syncthreads();

        const uint32_t bufo = (uint32_t)(kt & 1) * GBUF;
        #pragma unroll
        for (int h16 = 0; h16 < 2; h16++) {
            uint32_t ah[4][4], al[4][4];
            #pragma unroll
            for (int mi = 0; mi < 4; mi++) {
                int row = wm * 64 + mi * 16 + grp;
                uint32_t base = sb + bufo + row * 80 + h16 * 32 + tig * 4;
                ah[mi][0] = lds32(base);
                ah[mi][1] = lds32(base + 8 * 80);
                ah[mi][2] = lds32(base + 16);
                ah[mi][3] = lds32(base + 8 * 80 + 16);
                al[mi][0] = lds32(base + GT_BYTES);
                al[mi][1] = lds32(base + GT_BYTES + 8 * 80);
                al[mi][2] = lds32(base + GT_BYTES + 16);
                al[mi][3] = lds32(base + GT_BYTES + 8 * 80 + 16);
            }
            uint32_t bh[4][2], bl[4][2];
            #pragma unroll
            for (int ni = 0; ni < 4; ni++) {
                int row = wn * 32 + ni * 8 + grp;
                uint32_t base = sb + bufo + 2 * GT_BYTES + row * 80 + h16 * 32 + tig * 4;
                bh[ni][0] = lds32(base);
                bh[ni][1] = lds32(base + 16);
                bl[ni][0] = lds32(base + GT_BYTES);
                bl[ni][1] = lds32(base + GT_BYTES + 16);
            }
            #pragma unroll
            for (int mi = 0; mi < 4; mi++)
                #pragma unroll
                for (int ni = 0; ni < 4; ni++) {
                    float* a = acc[mi][ni];
                    mma16816h(a[0], a[1], a[2], a[3],
                              ah[mi][0], ah[mi][1], ah[mi][2], ah[mi][3],
                              bh[ni][0], bh[ni][1]);
                    mma16816h(a[0], a[1], a[2], a[3],
                              ah[mi][0], ah[mi][1], ah[mi][2], ah[mi][3],
                              bl[ni][0], bl[ni][1]);
                    mma16816h(a[0], a[1], a[2], a[3],
                              al[mi][0], al[mi][1], al[mi][2], al[mi][3],
                              bh[ni][0], bh[ni][1]);
                }
        }
        __syncthreads();
    }

    #pragma unroll
    for (int ni = 0; ni < 4; ni++) {
        int gc = n0 + wn * 32 + ni * 8 + tig * 2;
        float bs0 = 0.f, bs1 = 0.f;
        if (bias1) { bs0 += bias1[gc]; bs1 += bias1[gc + 1]; }
        if (bias2) { bs0 += bias2[gc]; bs1 += bias2[gc + 1]; }
        #pragma unroll
        for (int mi = 0; mi < 4; mi++) {
            int gr = m0 + wm * 64 + mi * 16 + grp;
            float* a = acc[mi][ni];
            *(float2*)&C[(size_t)gr * N + gc] = make_float2(a[0] + bs0, a[1] + bs1);
            *(float2*)&C[(size_t)(gr + 8) * N + gc] = make_float2(a[2] + bs0, a[3] + bs1);
        }
    }
}

// ---------------- row softmax over 512 cols ---------------------------------
__global__ __launch_bounds__(256)
void softmax512(const float* __restrict__ logits, float* __restrict__ out)
{
    const int row = blockIdx.x;
    const int tid = threadIdx.x;
    const float* in = logits + (size_t)row * OO;
    float a = in[tid], b = in[tid + 256];

    float m = fmaxf(a, b);
    #pragma unroll
    for (int o = 16; o > 0; o >>= 1)
        m = fmaxf(m, __shfl_xor_sync(0xffffffffu, m, o));
    __shared__ float redm[8];
    __shared__ float reds[8];
    if ((tid & 31) == 0) redm[tid >> 5] = m;
    __syncthreads();
    float mm = redm[0];
    #pragma unroll
    for (int i = 1; i < 8; i++) mm = fmaxf(mm, redm[i]);

    float e0 = expf(a - mm), e1 = expf(b - mm);
    float s = e0 + e1;
    #pragma unroll
    for (int o = 16; o > 0; o >>= 1)
        s += __shfl_xor_sync(0xffffffffu, s, o);
    if ((tid & 31) == 0) reds[tid >> 5] = s;
    __syncthreads();
    float ss = 0.f;
    #pragma unroll
    for (int i = 0; i < 8; i++) ss += reds[i];
    float inv = 1.0f / ss;

    float* op = out + (size_t)row * OO;
    op[tid]       = e0 * inv;
    op[tid + 256] = e1 * inv;
}

// ---------------- launch -----------------------------------------------------
extern "C" void kernel_launch(void* const* d_in, const int* in_sizes, int n_in,
                              void* d_out, int out_size)
{
    const float* x     = (const float*)d_in[0];
    const float* h0    = (const float*)d_in[1];
    const float* W_ih  = (const float*)d_in[2];
    const float* W_hh  = (const float*)d_in[3];
    const float* b_ih  = (const float*)d_in[4];
    const float* b_hh  = (const float*)d_in[5];
    const float* W_out = (const float*)d_in[6];
    const float* b_out = (const float*)d_in[7];
    float* out = (float*)d_out;

    float *pre, *logits, *zfb;
    cudaGetSymbolAddress((void**)&pre,    g_pre);
    cudaGetSymbolAddress((void**)&logits, g_logits);
    cudaGetSymbolAddress((void**)&zfb,    g_zfallback);
    __half *xh, *xl, *wihh, *wihl, *wouth, *woutl, *zh16, *zl16;
    cudaGetSymbolAddress((void**)&xh, g_xh);
    cudaGetSymbolAddress((void**)&xl, g_xl);
    cudaGetSymbolAddress((void**)&wihh, g_wihh);
    cudaGetSymbolAddress((void**)&wihl, g_wihl);
    cudaGetSymbolAddress((void**)&wouth, g_wouth);
    cudaGetSymbolAddress((void**)&woutl, g_woutl);
    cudaGetSymbolAddress((void**)&zh16, g_zh16);
    cudaGetSymbolAddress((void**)&zl16, g_zl16);

    cudaFuncSetAttribute(hgemm, cudaFuncAttributeMaxDynamicSharedMemorySize, GSMEM);
    cudaFuncSetAttribute(rnn_persistent, cudaFuncAttributeMaxDynamicSharedMemorySize, RNN_SMEM);

    float* z = (out_size >= (int)((size_t)MM * (OO + HH)))
                 ? out + (size_t)MM * OO : zfb;

    // 0) fused prep: fp16-pair splits of x/W_ih/W_out + h0 convert
    prep_all<<<592, 256>>>(x, W_ih, W_out, h0);

    // 1) pre = x @ W_ih^T + b_ih + b_hh   (fp16-pair 3-term)
    dim3 g1(MM / 128, HH / 128);
    hgemm<<<g1, 256, GSMEM>>>(MM, HH, II, xh, xl, wihh, wihl, b_ih, b_hh, pre);

    // 2) recurrence (persistent, fp16 state, 2-store phase B)
    rnn_persistent<<<RNN_BLOCKS, 256, RNN_SMEM>>>(pre, W_hh, z);

    // 3) z -> fp16 hi/lo (off the critical chain)
    zsplit<<<(MM * HH + 255) / 256, 256>>>(z);

    // 4) logits = z @ W_out^T + b_out   (fp16-pair 3-term)
    dim3 g3(MM / 128, OO / 128);
    hgemm<<<g3, 256, GSMEM>>>(MM, OO, HH, zh16, zl16, wouth, woutl, b_out, nullptr, logits);

    // 5) softmax rows -> out
    softmax512<<<MM, 256>>>(logits, out);
}

// round 15
// speedup vs baseline: 1.0241x; 1.0241x over previous
#include <cuda_runtime.h>
#include <cuda_bf16.h>
#include <cuda_fp16.h>
#include <cstdint>

// Problem dims
#define BB   32
#define TT   512
#define II   512
#define HH   1024
#define OO   512
#define MM   (BB*TT)

#define RNN_BLOCKS 64

// ---------------- scratch (static device globals) ---------------------------
__device__ float g_pre[MM * HH];
__device__ float g_logits[MM * OO];
__device__ float g_zfallback[MM * HH];

__device__ __half g_xh[MM * II],    g_xl[MM * II];
__device__ __half g_wihh[HH * II],  g_wihl[HH * II];
__device__ __half g_wouth[OO * HH], g_woutl[OO * HH];
__device__ __half g_zh16[MM * HH];
__device__ __half g_h0h16[BB * HH];

// per-(block, mw-half) spread flags (128B apart)
__device__ unsigned g_flags[RNN_BLOCKS * 2 * 32];

// ---------------- helpers ----------------------------------------------------
__device__ __forceinline__ void mma16816h(float& d0, float& d1, float& d2, float& d3,
                                          uint32_t a0, uint32_t a1, uint32_t a2, uint32_t a3,
                                          uint32_t b0, uint32_t b1)
{
    asm volatile(
        "mma.sync.aligned.m16n8k16.row.col.f32.f16.f16.f32 "
        "{%0,%1,%2,%3},{%4,%5,%6,%7},{%8,%9},{%0,%1,%2,%3};"
        : "+f"(d0), "+f"(d1), "+f"(d2), "+f"(d3)
        : "r"(a0), "r"(a1), "r"(a2), "r"(a3), "r"(b0), "r"(b1));
}

__device__ __forceinline__ void ldsm4(uint32_t& r0, uint32_t& r1, uint32_t& r2, uint32_t& r3,
                                      uint32_t addr)
{
    asm volatile("ldmatrix.sync.aligned.m8n8.x4.shared.b16 {%0,%1,%2,%3}, [%4];"
                 : "=r"(r0), "=r"(r1), "=r"(r2), "=r"(r3) : "r"(addr));
}

__device__ __forceinline__ uint32_t lds32(uint32_t a) {
    uint32_t v;
    asm volatile("ld.shared.b32 %0, [%1];" : "=r"(v) : "r"(a));
    return v;
}

__device__ __forceinline__ void cpa16(uint32_t s, const void* g) {
    asm volatile("cp.async.cg.shared.global [%0], [%1], 16;" :: "r"(s), "l"(g));
}

__device__ __forceinline__ uint32_t pack_h2(float x, float y) {
    __half2 t = __floats2half2_rn(x, y);
    return *reinterpret_cast<uint32_t*>(&t);
}

__device__ __forceinline__ void flag_store(unsigned* p, unsigned v) {
    asm volatile("st.release.gpu.u32 [%0], %1;" :: "l"(p), "r"(v));
}
__device__ __forceinline__ void flag_wait(const unsigned* p, unsigned target) {
    unsigned v;
    do {
        asm volatile("ld.acquire.gpu.u32 %0, [%1];" : "=r"(v) : "l"(p));
    } while ((int)(v - target) < 0);
}

__device__ __forceinline__ void nbar_sync(int id, int cnt) {
    asm volatile("bar.sync %0, %1;" :: "r"(id), "r"(cnt) : "memory");
}
__device__ __forceinline__ void nbar_arrive(int id, int cnt) {
    asm volatile("bar.arrive %0, %1;" :: "r"(id), "r"(cnt) : "memory");
}

// ---------------- persistent Elman recurrence (fp16 state, dataflow) ---------
#define WBUF   8448                    // per-warp fp16 slice
#define SM_PS  (8 * WBUF)              // 67584
#define PSROW  18
#define PS_KW  (16 * PSROW)
#define PS_HALF (4 * PS_KW)
#define RNN_SMEM (SM_PS + 2 * 2 * PS_HALF * 4)

__global__ __launch_bounds__(256, 1)
void rnn_persistent(const float* __restrict__ pre,
                    const float* __restrict__ W_hh,
                    float* __restrict__ z_out)
{
    extern __shared__ __align__(16) char dsm[];
    const uint32_t sb = (uint32_t)__cvta_generic_to_shared(dsm);

    const int tid  = threadIdx.x;
    const int wid  = tid >> 5;
    const int lane = tid & 31;
    const int grp  = lane >> 2;       // 0..7
    const int tig  = lane & 3;        // 0..3
    const int jc   = blockIdx.x;      // 0..63
    const int kw   = wid & 3;         // k chunk of 256
    const int mw   = wid >> 2;        // b half

    // replay-safe base (all flags equal at launch start)
    const unsigned base = g_flags[blockIdx.x * 64];

    // ---- preload W fragments (fp16) into registers, whole run ----
    uint32_t w0[2][16], w1[2][16];
    #pragma unroll
    for (int nt = 0; nt < 2; nt++) {
        const int jrow = jc * 16 + nt * 8 + grp;
        const float* Wr = W_hh + (size_t)jrow * HH + kw * 256;
        #pragma unroll
        for (int ki = 0; ki < 16; ki++) {
            int k0 = ki * 16 + tig * 2;
            w0[nt][ki] = pack_h2(Wr[k0],     Wr[k0 + 1]);
            w1[nt][ki] = pack_h2(Wr[k0 + 8], Wr[k0 + 9]);
        }
    }

    // warp-private staging buffer
    const uint32_t wb = sb + (uint32_t)wid * WBUF;
    const uint32_t lrow = (lane & 7) + ((lane >> 3) & 1) * 8;
    const uint32_t aoff = lrow * 528 + ((uint32_t)lane >> 4) * 16;

    // producer half-flag this lane polls: 16 producers cover k in [kw*256,+256)
    const int pflag = ((kw * 16 + (lane & 15)) * 2 + mw) * 32;

    // phase-B mapping within the 128-thread half
    const int ltid = tid & 127;
    const int lb   = ltid >> 3;               // local b 0..15
    const int pbB  = mw * 16 + lb;            // global b
    const int pbJ  = (ltid & 7) * 2;          // j pair within chunk

    float* const psum = (float*)(dsm + SM_PS);   // [parity][mw][kw][16][PSROW]

    const int barA = 1 + mw;   // psum-ready
    const int barB = 3 + mw;   // z-done

    for (int t = 0; t < TT; t++) {
        // prefetch pre (phase-B input, independent of h)
        float2 pre2 = *(const float2*)&pre[((size_t)pbB * TT + t) * HH + jc * 16 + pbJ];

        // ---- dataflow wait: this warp's 16 producer half-flags ----
        if (t > 0)
            flag_wait(&g_flags[pflag], base + (unsigned)t);
        __syncwarp();

        // ---- stage own 16-row x 256-k fp16 slice ----
        {
            const __half* sh;
            size_t rstride, off0;
            if (t == 0) {
                sh = g_h0h16;
                rstride = HH;
                off0 = (size_t)(mw * 16) * HH + kw * 256;
            } else {
                sh = g_zh16;
                rstride = (size_t)TT * HH;
                off0 = ((size_t)(mw * 16) * TT + (t - 1)) * HH + kw * 256;
            }
            #pragma unroll
            for (int i = 0; i < 16; i++) {
                int chunk = i * 32 + lane;
                int row   = chunk >> 5;
                int c     = chunk & 31;
                cpa16(wb + row * 528 + c * 16, sh + off0 + (size_t)row * rstride + c * 8);
            }
            asm volatile("cp.async.commit_group;" ::: "memory");
            asm volatile("cp.async.wait_group 0;" ::: "memory");
            __syncwarp();
        }

        // ---- mma over own k=256 (single fp16 term) ----
        float a1[2][4] = {{0,0,0,0},{0,0,0,0}};
        #pragma unroll
        for (int ki = 0; ki < 16; ki++) {
            uint32_t h0r, h1r, h2r, h3r;
            ldsm4(h0r, h1r, h2r, h3r, wb + aoff + ki * 32);
            #pragma unroll
            for (int nt = 0; nt < 2; nt++) {
                mma16816h(a1[nt][0], a1[nt][1], a1[nt][2], a1[nt][3],
                          h0r, h1r, h2r, h3r, w0[nt][ki], w1[nt][ki]);
            }
        }

        // ---- per-warp k-partials to SMEM (parity double-buffered) ----
        {
            float* pb = psum + ((t & 1) * 2 + mw) * PS_HALF + kw * PS_KW;
            #pragma unroll
            for (int nt = 0; nt < 2; nt++) {
                int jj = nt * 8 + tig * 2;
                float* p = pb + grp * PSROW + jj;
                *(float2*)p               = make_float2(a1[nt][0], a1[nt][1]);
                *(float2*)(p + 8 * PSROW) = make_float2(a1[nt][2], a1[nt][3]);
            }
        }
        nbar_sync(barA, 128);   // psum ready within this half

        // ---- phase B (2 elements/thread): reduce 4 kw, tanh, publish ----
        // 2 stores only (zh16 + z fp32); no lo-state needed anywhere.
        {
            const float* pb = psum + ((t & 1) * 2 + mw) * PS_HALF;
            float s0 = pre2.x, s1 = pre2.y;
            #pragma unroll
            for (int kk = 0; kk < 4; kk++) {
                float2 p = *(float2*)&pb[kk * PS_KW + lb * PSROW + pbJ];
                s0 += p.x; s1 += p.y;
            }
            float h0v = tanhf(s0);
            float h1v = tanhf(s1);
            size_t zidx = ((size_t)pbB * TT + t) * HH + jc * 16 + pbJ;
            *(uint32_t*)&g_zh16[zidx] = pack_h2(h0v, h1v);
            *(float2*)&z_out[zidx]    = make_float2(h0v, h1v);
        }

        // ---- z-done: kw=0 warp syncs + publishes; others arrive & fly ----
        if (kw == 0) {
            nbar_sync(barB, 128);
            if (lane == 0)
                flag_store(&g_flags[(blockIdx.x * 2 + mw) * 32], base + (unsigned)t + 1u);
        } else {
            nbar_arrive(barB, 128);
        }
    }
}

// ---------------- fused prep: fp16-pair splits of x, W_ih, W_out; h0 conv ----
#define N_X   (MM * II)
#define N_WI  (HH * II)
#define N_WO  (OO * HH)
#define N_H0  (BB * HH)
#define N_PREP (N_X + N_WI + N_WO + N_H0)

__global__ __launch_bounds__(256)
void prep_all(const float* __restrict__ x, const float* __restrict__ W_ih,
              const float* __restrict__ W_out, const float* __restrict__ h0)
{
    int stride = gridDim.x * 256;
    for (int i = blockIdx.x * 256 + threadIdx.x; i < N_PREP; i += stride) {
        const float* src;
        __half *hi, *lo;
        int idx = i;
        if (idx < N_X)                    { src = x;     hi = g_xh;    lo = g_xl; }
        else if ((idx -= N_X) < N_WI)     { src = W_ih;  hi = g_wihh;  lo = g_wihl; }
        else if ((idx -= N_WI) < N_WO)    { src = W_out; hi = g_wouth; lo = g_woutl; }
        else { idx -= N_WO;
            g_h0h16[idx] = __float2half_rn(h0[idx]);
            continue;
        }
        float v = src[idx];
        __half h = __float2half_rn(v);
        hi[idx] = h;
        lo[idx] = __float2half_rn(v - __half2float(h));
    }
}

// ---------------- mma.sync fp16-pair GEMM ------------------------------------
// THREE=true : C = (Ah+Al)(Bh+Bl)^T approx via Ah*Bh + Ah*Bl + Al*Bh
// THREE=false: C = Ah*Bh + Ah*Bl   (A already rounded, e.g. z in fp16)
#define GT_BYTES  (128 * 80)
#define GBUF      (4 * GT_BYTES)
#define GSMEM     (2 * GBUF)

template <bool THREE>
__global__ __launch_bounds__(256)
void hgemm(int M, int N, int K,
           const __half* __restrict__ Ah, const __half* __restrict__ Al,
           const __half* __restrict__ Bh, const __half* __restrict__ Bl,
           const float* __restrict__ bias1, const float* __restrict__ bias2,
           float* __restrict__ C)
{
    extern __shared__ __align__(16) char dsm[];
    const uint32_t sb = (uint32_t)__cvta_generic_to_shared(dsm);

    const int tid  = threadIdx.x;
    const int wid  = tid >> 5;
    const int lane = tid & 31;
    const int grp  = lane >> 2;
    const int tig  = lane & 3;
    const int wm   = wid & 1;
    const int wn   = wid >> 1;
    const int m0   = blockIdx.x * 128;
    const int n0   = blockIdx.y * 128;

    float acc[4][4][4];
    #pragma unroll
    for (int i = 0; i < 4; i++)
        #pragma unroll
        for (int j = 0; j < 4; j++)
            #pragma unroll
            for (int q = 0; q < 4; q++) acc[i][j][q] = 0.f;

    const int lrow = tid >> 2;
    const int lc16 = tid & 3;

    auto issue = [&](int kt, int buf) {
        #pragma unroll
        for (int r = 0; r < 2; r++) {
            int row = lrow + r * 64;
            uint32_t so = (uint32_t)buf * GBUF + row * 80 + lc16 * 16;
            size_t goA = (size_t)(m0 + row) * K + kt * 32 + lc16 * 8;
            size_t goB = (size_t)(n0 + row) * K + kt * 32 + lc16 * 8;
            cpa16(sb + so,                Ah + goA);
            if (THREE)
                cpa16(sb + so + GT_BYTES, Al + goA);
            cpa16(sb + so + 2 * GT_BYTES, Bh + goB);
            cpa16(sb + so + 3 * GT_BYTES, Bl + goB);
        }
        asm volatile("cp.async.commit_group;" ::: "memory");
    };

    const int KT = K >> 5;
    issue(0, 0);

    for (int kt = 0; kt < KT; kt++) {
        if (kt + 1 < KT) {
            issue(kt + 1, (kt + 1) & 1);
            asm volatile("cp.async.wait_group 1;" ::: "memory");
        } else {
            asm volatile("cp.async.wait_group 0;" ::: "memory");
        }
        __syncthreads();

        const uint32_t bufo = (uint32_t)(kt & 1) * GBUF;
        #pragma unroll
        for (int h16 = 0; h16 < 2; h16++) {
            uint32_t ah[4][4], al[4][4];
            #pragma unroll
            for (int mi = 0; mi < 4; mi++) {
                int row = wm * 64 + mi * 16 + grp;
                uint32_t base = sb + bufo + row * 80 + h16 * 32 + tig * 4;
                ah[mi][0] = lds32(base);
                ah[mi][1] = lds32(base + 8 * 80);
                ah[mi][2] = lds32(base + 16);
                ah[mi][3] = lds32(base + 8 * 80 + 16);
                if (THREE) {
                    al[mi][0] = lds32(base + GT_BYTES);
                    al[mi][1] = lds32(base + GT_BYTES + 8 * 80);
                    al[mi][2] = lds32(base + GT_BYTES + 16);
                    al[mi][3] = lds32(base + GT_BYTES + 8 * 80 + 16);
                }
            }
            uint32_t bh[4][2], bl[4][2];
            #pragma unroll
            for (int ni = 0; ni < 4; ni++) {
                int row = wn * 32 + ni * 8 + grp;
                uint32_t base = sb + bufo + 2 * GT_BYTES + row * 80 + h16 * 32 + tig * 4;
                bh[ni][0] = lds32(base);
                bh[ni][1] = lds32(base + 16);
                bl[ni][0] = lds32(base + GT_BYTES);
                bl[ni][1] = lds32(base + GT_BYTES + 16);
            }
            #pragma unroll
            for (int mi = 0; mi < 4; mi++)
                #pragma unroll
                for (int ni = 0; ni < 4; ni++) {
                    float* a = acc[mi][ni];
                    mma16816h(a[0], a[1], a[2], a[3],
                              ah[mi][0], ah[mi][1], ah[mi][2], ah[mi][3],
                              bh[ni][0], bh[ni][1]);
                    mma16816h(a[0], a[1], a[2], a[3],
                              ah[mi][0], ah[mi][1], ah[mi][2], ah[mi][3],
                              bl[ni][0], bl[ni][1]);
                    if (THREE)
                        mma16816h(a[0], a[1], a[2], a[3],
                                  al[mi][0], al[mi][1], al[mi][2], al[mi][3],
                                  bh[ni][0], bh[ni][1]);
                }
        }
        __syncthreads();
    }

    #pragma unroll
    for (int ni = 0; ni < 4; ni++) {
        int gc = n0 + wn * 32 + ni * 8 + tig * 2;
        float bs0 = 0.f, bs1 = 0.f;
        if (bias1) { bs0 += bias1[gc]; bs1 += bias1[gc + 1]; }
        if (bias2) { bs0 += bias2[gc]; bs1 += bias2[gc + 1]; }
        #pragma unroll
        for (int mi = 0; mi < 4; mi++) {
            int gr = m0 + wm * 64 + mi * 16 + grp;
            float* a = acc[mi][ni];
            *(float2*)&C[(size_t)gr * N + gc] = make_float2(a[0] + bs0, a[1] + bs1);
            *(float2*)&C[(size_t)(gr + 8) * N + gc] = make_float2(a[2] + bs0, a[3] + bs1);
        }
    }
}

// ---------------- row softmax over 512 cols ---------------------------------
__global__ __launch_bounds__(256)
void softmax512(const float* __restrict__ logits, float* __restrict__ out)
{
    const int row = blockIdx.x;
    const int tid = threadIdx.x;
    const float* in = logits + (size_t)row * OO;
    float a = in[tid], b = in[tid + 256];

    float m = fmaxf(a, b);
    #pragma unroll
    for (int o = 16; o > 0; o >>= 1)
        m = fmaxf(m, __shfl_xor_sync(0xffffffffu, m, o));
    __shared__ float redm[8];
    __shared__ float reds[8];
    if ((tid & 31) == 0) redm[tid >> 5] = m;
    __syncthreads();
    float mm = redm[0];
    #pragma unroll
    for (int i = 1; i < 8; i++) mm = fmaxf(mm, redm[i]);

    float e0 = expf(a - mm), e1 = expf(b - mm);
    float s = e0 + e1;
    #pragma unroll
    for (int o = 16; o > 0; o >>= 1)
        s += __shfl_xor_sync(0xffffffffu, s, o);
    if ((tid & 31) == 0) reds[tid >> 5] = s;
    __syncthreads();
    float ss = 0.f;
    #pragma unroll
    for (int i = 0; i < 8; i++) ss += reds[i];
    float inv = 1.0f / ss;

    float* op = out + (size_t)row * OO;
    op[tid]       = e0 * inv;
    op[tid + 256] = e1 * inv;
}

// ---------------- launch -----------------------------------------------------
extern "C" void kernel_launch(void* const* d_in, const int* in_sizes, int n_in,
                              void* d_out, int out_size)
{
    const float* x     = (const float*)d_in[0];
    const float* h0    = (const float*)d_in[1];
    const float* W_ih  = (const float*)d_in[2];
    const float* W_hh  = (const float*)d_in[3];
    const float* b_ih  = (const float*)d_in[4];
    const float* b_hh  = (const float*)d_in[5];
    const float* W_out = (const float*)d_in[6];
    const float* b_out = (const float*)d_in[7];
    float* out = (float*)d_out;

    float *pre, *logits, *zfb;
    cudaGetSymbolAddress((void**)&pre,    g_pre);
    cudaGetSymbolAddress((void**)&logits, g_logits);
    cudaGetSymbolAddress((void**)&zfb,    g_zfallback);
    __half *xh, *xl, *wihh, *wihl, *wouth, *woutl, *zh16;
    cudaGetSymbolAddress((void**)&xh, g_xh);
    cudaGetSymbolAddress((void**)&xl, g_xl);
    cudaGetSymbolAddress((void**)&wihh, g_wihh);
    cudaGetSymbolAddress((void**)&wihl, g_wihl);
    cudaGetSymbolAddress((void**)&wouth, g_wouth);
    cudaGetSymbolAddress((void**)&woutl, g_woutl);
    cudaGetSymbolAddress((void**)&zh16, g_zh16);

    cudaFuncSetAttribute(hgemm<true>,  cudaFuncAttributeMaxDynamicSharedMemorySize, GSMEM);
    cudaFuncSetAttribute(hgemm<false>, cudaFuncAttributeMaxDynamicSharedMemorySize, GSMEM);
    cudaFuncSetAttribute(rnn_persistent, cudaFuncAttributeMaxDynamicSharedMemorySize, RNN_SMEM);

    float* z = (out_size >= (int)((size_t)MM * (OO + HH)))
                 ? out + (size_t)MM * OO : zfb;

    // 0) fused prep: fp16-pair splits of x/W_ih/W_out + h0 convert
    prep_all<<<592, 256>>>(x, W_ih, W_out, h0);

    // 1) pre = x @ W_ih^T + b_ih + b_hh   (3-term: x needs its lo)
    dim3 g1(MM / 128, HH / 128);
    hgemm<true><<<g1, 256, GSMEM>>>(MM, HH, II, xh, xl, wihh, wihl, b_ih, b_hh, pre);

    // 2) recurrence (persistent, fp16 state, 2-store phase B)
    rnn_persistent<<<RNN_BLOCKS, 256, RNN_SMEM>>>(pre, W_hh, z);

    // 3) logits = z @ W_out^T + b_out   (2-term: zh only; W keeps lo)
    dim3 g3(MM / 128, OO / 128);
    hgemm<false><<<g3, 256, GSMEM>>>(MM, OO, HH, zh16, nullptr, wouth, woutl, b_out, nullptr, logits);

    // 4) softmax rows -> out
    softmax512<<<MM, 256>>>(logits, out);
}

// round 16
// speedup vs baseline: 1.0760x; 1.0507x over previous
#include <cuda_runtime.h>
#include <cuda_bf16.h>
#include <cuda_fp16.h>
#include <cstdint>

// Problem dims
#define BB   32
#define TT   512
#define II   512
#define HH   1024
#define OO   512
#define MM   (BB*TT)

#define RNN_BLOCKS 64

// ---------------- scratch (static device globals) ---------------------------
__device__ float g_pre[MM * HH];
__device__ float g_logits[MM * OO];
__device__ float g_zfallback[MM * HH];

__device__ __half g_xh[MM * II],    g_xl[MM * II];
__device__ __half g_wihh[HH * II],  g_wihl[HH * II];
__device__ __half g_wouth[OO * HH], g_woutl[OO * HH];
__device__ __half g_zh16[MM * HH];
__device__ __half g_h0h16[BB * HH];

// per-(block, mw-half) spread flags (128B apart)
__device__ unsigned g_flags[RNN_BLOCKS * 2 * 32];

// ---------------- helpers ----------------------------------------------------
__device__ __forceinline__ void mma16816h(float& d0, float& d1, float& d2, float& d3,
                                          uint32_t a0, uint32_t a1, uint32_t a2, uint32_t a3,
                                          uint32_t b0, uint32_t b1)
{
    asm volatile(
        "mma.sync.aligned.m16n8k16.row.col.f32.f16.f16.f32 "
        "{%0,%1,%2,%3},{%4,%5,%6,%7},{%8,%9},{%0,%1,%2,%3};"
        : "+f"(d0), "+f"(d1), "+f"(d2), "+f"(d3)
        : "r"(a0), "r"(a1), "r"(a2), "r"(a3), "r"(b0), "r"(b1));
}

__device__ __forceinline__ void ldsm4(uint32_t& r0, uint32_t& r1, uint32_t& r2, uint32_t& r3,
                                      uint32_t addr)
{
    asm volatile("ldmatrix.sync.aligned.m8n8.x4.shared.b16 {%0,%1,%2,%3}, [%4];"
                 : "=r"(r0), "=r"(r1), "=r"(r2), "=r"(r3) : "r"(addr));
}

__device__ __forceinline__ uint32_t lds32(uint32_t a) {
    uint32_t v;
    asm volatile("ld.shared.b32 %0, [%1];" : "=r"(v) : "r"(a));
    return v;
}

__device__ __forceinline__ void cpa16(uint32_t s, const void* g) {
    asm volatile("cp.async.cg.shared.global [%0], [%1], 16;" :: "r"(s), "l"(g));
}

__device__ __forceinline__ uint32_t pack_h2(float x, float y) {
    __half2 t = __floats2half2_rn(x, y);
    return *reinterpret_cast<uint32_t*>(&t);
}

__device__ __forceinline__ void flag_store(unsigned* p, unsigned v) {
    asm volatile("st.release.gpu.u32 [%0], %1;" :: "l"(p), "r"(v));
}
__device__ __forceinline__ void flag_wait(const unsigned* p, unsigned target) {
    unsigned v;
    do {
        asm volatile("ld.acquire.gpu.u32 %0, [%1];" : "=r"(v) : "l"(p));
    } while ((int)(v - target) < 0);
}

__device__ __forceinline__ void nbar_sync(int id, int cnt) {
    asm volatile("bar.sync %0, %1;" :: "r"(id), "r"(cnt) : "memory");
}
__device__ __forceinline__ void nbar_arrive(int id, int cnt) {
    asm volatile("bar.arrive %0, %1;" :: "r"(id), "r"(cnt) : "memory");
}

// ---------------- persistent Elman recurrence (fp16 state, dataflow) ---------
#define WBUF   8448                    // per-warp fp16 slice
#define SM_PS  (8 * WBUF)              // 67584
#define PSROW  18
#define PS_KW  (16 * PSROW)
#define PS_HALF (4 * PS_KW)
#define RNN_SMEM (SM_PS + 2 * 2 * PS_HALF * 4)

__global__ __launch_bounds__(256, 1)
void rnn_persistent(const float* __restrict__ pre,
                    const float* __restrict__ W_hh,
                    float* __restrict__ z_out)
{
    extern __shared__ __align__(16) char dsm[];
    const uint32_t sb = (uint32_t)__cvta_generic_to_shared(dsm);

    const int tid  = threadIdx.x;
    const int wid  = tid >> 5;
    const int lane = tid & 31;
    const int grp  = lane >> 2;       // 0..7
    const int tig  = lane & 3;        // 0..3
    const int jc   = blockIdx.x;      // 0..63
    const int kw   = wid & 3;         // k chunk of 256
    const int mw   = wid >> 2;        // b half

    // replay-safe base (all flags equal at launch start)
    const unsigned base = g_flags[blockIdx.x * 64];

    // ---- preload W fragments (fp16) into registers, whole run ----
    uint32_t w0[2][16], w1[2][16];
    #pragma unroll
    for (int nt = 0; nt < 2; nt++) {
        const int jrow = jc * 16 + nt * 8 + grp;
        const float* Wr = W_hh + (size_t)jrow * HH + kw * 256;
        #pragma unroll
        for (int ki = 0; ki < 16; ki++) {
            int k0 = ki * 16 + tig * 2;
            w0[nt][ki] = pack_h2(Wr[k0],     Wr[k0 + 1]);
            w1[nt][ki] = pack_h2(Wr[k0 + 8], Wr[k0 + 9]);
        }
    }

    // warp-private staging buffer
    const uint32_t wb = sb + (uint32_t)wid * WBUF;
    const uint32_t lrow = (lane & 7) + ((lane >> 3) & 1) * 8;
    const uint32_t aoff = lrow * 528 + ((uint32_t)lane >> 4) * 16;

    // producer half-flag this lane polls: 16 producers cover k in [kw*256,+256)
    const int pflag = ((kw * 16 + (lane & 15)) * 2 + mw) * 32;

    // phase-B mapping within the 128-thread half
    const int ltid = tid & 127;
    const int lb   = ltid >> 3;               // local b 0..15
    const int pbB  = mw * 16 + lb;            // global b
    const int pbJ  = (ltid & 7) * 2;          // j pair within chunk

    float* const psum = (float*)(dsm + SM_PS);   // [parity][mw][kw][16][PSROW]

    const int barA = 1 + mw;   // psum-ready
    const int barB = 3 + mw;   // z-done

    for (int t = 0; t < TT; t++) {
        // prefetch pre (phase-B input, independent of h)
        float2 pre2 = *(const float2*)&pre[((size_t)pbB * TT + t) * HH + jc * 16 + pbJ];

        // ---- dataflow wait: this warp's 16 producer half-flags ----
        if (t > 0)
            flag_wait(&g_flags[pflag], base + (unsigned)t);
        __syncwarp();

        // ---- stage own 16-row x 256-k fp16 slice ----
        {
            const __half* sh;
            size_t rstride, off0;
            if (t == 0) {
                sh = g_h0h16;
                rstride = HH;
                off0 = (size_t)(mw * 16) * HH + kw * 256;
            } else {
                sh = g_zh16;
                rstride = (size_t)TT * HH;
                off0 = ((size_t)(mw * 16) * TT + (t - 1)) * HH + kw * 256;
            }
            #pragma unroll
            for (int i = 0; i < 16; i++) {
                int chunk = i * 32 + lane;
                int row   = chunk >> 5;
                int c     = chunk & 31;
                cpa16(wb + row * 528 + c * 16, sh + off0 + (size_t)row * rstride + c * 8);
            }
            asm volatile("cp.async.commit_group;" ::: "memory");
            asm volatile("cp.async.wait_group 0;" ::: "memory");
            __syncwarp();
        }

        // ---- mma over own k=256 (single fp16 term) ----
        float a1[2][4] = {{0,0,0,0},{0,0,0,0}};
        #pragma unroll
        for (int ki = 0; ki < 16; ki++) {
            uint32_t h0r, h1r, h2r, h3r;
            ldsm4(h0r, h1r, h2r, h3r, wb + aoff + ki * 32);
            #pragma unroll
            for (int nt = 0; nt < 2; nt++) {
                mma16816h(a1[nt][0], a1[nt][1], a1[nt][2], a1[nt][3],
                          h0r, h1r, h2r, h3r, w0[nt][ki], w1[nt][ki]);
            }
        }

        // ---- per-warp k-partials to SMEM (parity double-buffered) ----
        {
            float* pb = psum + ((t & 1) * 2 + mw) * PS_HALF + kw * PS_KW;
            #pragma unroll
            for (int nt = 0; nt < 2; nt++) {
                int jj = nt * 8 + tig * 2;
                float* p = pb + grp * PSROW + jj;
                *(float2*)p               = make_float2(a1[nt][0], a1[nt][1]);
                *(float2*)(p + 8 * PSROW) = make_float2(a1[nt][2], a1[nt][3]);
            }
        }
        nbar_sync(barA, 128);   // psum ready within this half

        // ---- phase B (2 elements/thread): reduce 4 kw, tanh, publish ----
        {
            const float* pb = psum + ((t & 1) * 2 + mw) * PS_HALF;
            float s0 = pre2.x, s1 = pre2.y;
            #pragma unroll
            for (int kk = 0; kk < 4; kk++) {
                float2 p = *(float2*)&pb[kk * PS_KW + lb * PSROW + pbJ];
                s0 += p.x; s1 += p.y;
            }
            float h0v = tanhf(s0);
            float h1v = tanhf(s1);
            size_t zidx = ((size_t)pbB * TT + t) * HH + jc * 16 + pbJ;
            *(uint32_t*)&g_zh16[zidx] = pack_h2(h0v, h1v);
            *(float2*)&z_out[zidx]    = make_float2(h0v, h1v);
        }

        // ---- z-done: kw=0 warp syncs + publishes; others arrive & fly ----
        if (kw == 0) {
            nbar_sync(barB, 128);
            if (lane == 0)
                flag_store(&g_flags[(blockIdx.x * 2 + mw) * 32], base + (unsigned)t + 1u);
        } else {
            nbar_arrive(barB, 128);
        }
    }
}

// ---------------- fused prep: fp16-pair splits of x, W_ih, W_out; h0 conv ----
#define N_X   (MM * II)
#define N_WI  (HH * II)
#define N_WO  (OO * HH)
#define N_H0  (BB * HH)
#define N_PREP (N_X + N_WI + N_WO + N_H0)

__global__ __launch_bounds__(256)
void prep_all(const float* __restrict__ x, const float* __restrict__ W_ih,
              const float* __restrict__ W_out, const float* __restrict__ h0)
{
    int stride = gridDim.x * 256;
    for (int i = blockIdx.x * 256 + threadIdx.x; i < N_PREP; i += stride) {
        const float* src;
        __half *hi, *lo;
        int idx = i;
        if (idx < N_X)                    { src = x;     hi = g_xh;    lo = g_xl; }
        else if ((idx -= N_X) < N_WI)     { src = W_ih;  hi = g_wihh;  lo = g_wihl; }
        else if ((idx -= N_WI) < N_WO)    { src = W_out; hi = g_wouth; lo = g_woutl; }
        else { idx -= N_WO;
            g_h0h16[idx] = __float2half_rn(h0[idx]);
            continue;
        }
        float v = src[idx];
        __half h = __float2half_rn(v);
        hi[idx] = h;
        lo[idx] = __float2half_rn(v - __half2float(h));
    }
}

// ---------------- mma.sync fp16-pair GEMM, 128x64 tile (2 CTAs/SM) -----------
// THREE=true : C = Ah*Bh + Ah*Bl + Al*Bh
// THREE=false: C = Ah*Bh + Ah*Bl   (A already rounded)
// 256 threads, 8 warps: wm=wid>>1 (32-row slice of 128), wn=wid&1 (32-col of 64)
#define GA_BYTES  (128 * 80)      // A tile (one term)
#define GB_BYTES  (64 * 80)       // B tile (one term)
#define GBUF      (2 * GA_BYTES + 2 * GB_BYTES)   // Ah|Al|Bh|Bl = 30720
#define OFF_AL    GA_BYTES
#define OFF_BH    (2 * GA_BYTES)
#define OFF_BL    (2 * GA_BYTES + GB_BYTES)
#define GSMEM     (2 * GBUF)      // 61440

template <bool THREE>
__global__ __launch_bounds__(256)
void hgemm(int M, int N, int K,
           const __half* __restrict__ Ah, const __half* __restrict__ Al,
           const __half* __restrict__ Bh, const __half* __restrict__ Bl,
           const float* __restrict__ bias1, const float* __restrict__ bias2,
           float* __restrict__ C)
{
    extern __shared__ __align__(16) char dsm[];
    const uint32_t sb = (uint32_t)__cvta_generic_to_shared(dsm);

    const int tid  = threadIdx.x;
    const int wid  = tid >> 5;
    const int lane = tid & 31;
    const int grp  = lane >> 2;
    const int tig  = lane & 3;
    const int wm   = wid >> 1;      // 0..3 : 32-row slice
    const int wn   = wid & 1;       // 0..1 : 32-col slice
    const int m0   = blockIdx.x * 128;
    const int n0   = blockIdx.y * 64;

    float acc[2][4][4];
    #pragma unroll
    for (int i = 0; i < 2; i++)
        #pragma unroll
        for (int j = 0; j < 4; j++)
            #pragma unroll
            for (int q = 0; q < 4; q++) acc[i][j][q] = 0.f;

    // loaders: A 128 rows x 4 chunks (512), B 64 rows x 4 chunks (256)
    const int lrowA = tid >> 1;          // with r-loop: rows 0..127
    const int lrowB = tid >> 2;          // 0..63
    const int lcB   = tid & 3;

    auto issue = [&](int kt, int buf) {
        // A: 2 passes of 256 chunks (row = idx>>2, c16 = idx&3)
        #pragma unroll
        for (int r = 0; r < 2; r++) {
            int idx = tid + r * 256;
            int row = idx >> 2;
            int c16 = idx & 3;
            uint32_t so = (uint32_t)buf * GBUF + row * 80 + c16 * 16;
            size_t go  = (size_t)(m0 + row) * K + kt * 32 + c16 * 8;
            cpa16(sb + so, Ah + go);
            if (THREE)
                cpa16(sb + so + OFF_AL, Al + go);
        }
        // B: 256 chunks
        {
            uint32_t so = (uint32_t)buf * GBUF + lrowB * 80 + lcB * 16;
            size_t go  = (size_t)(n0 + lrowB) * K + kt * 32 + lcB * 8;
            cpa16(sb + so + OFF_BH, Bh + go);
            cpa16(sb + so + OFF_BL, Bl + go);
        }
        asm volatile("cp.async.commit_group;" ::: "memory");
    };

    const int KT = K >> 5;
    issue(0, 0);

    for (int kt = 0; kt < KT; kt++) {
        if (kt + 1 < KT) {
            issue(kt + 1, (kt + 1) & 1);
            asm volatile("cp.async.wait_group 1;" ::: "memory");
        } else {
            asm volatile("cp.async.wait_group 0;" ::: "memory");
        }
        __syncthreads();

        const uint32_t bufo = (uint32_t)(kt & 1) * GBUF;
        #pragma unroll
        for (int h16 = 0; h16 < 2; h16++) {
            uint32_t ah[2][4], al[2][4];
            #pragma unroll
            for (int mi = 0; mi < 2; mi++) {
                int row = wm * 32 + mi * 16 + grp;
                uint32_t base = sb + bufo + row * 80 + h16 * 32 + tig * 4;
                ah[mi][0] = lds32(base);
                ah[mi][1] = lds32(base + 8 * 80);
                ah[mi][2] = lds32(base + 16);
                ah[mi][3] = lds32(base + 8 * 80 + 16);
                if (THREE) {
                    al[mi][0] = lds32(base + OFF_AL);
                    al[mi][1] = lds32(base + OFF_AL + 8 * 80);
                    al[mi][2] = lds32(base + OFF_AL + 16);
                    al[mi][3] = lds32(base + OFF_AL + 8 * 80 + 16);
                }
            }
            uint32_t bh[4][2], bl[4][2];
            #pragma unroll
            for (int ni = 0; ni < 4; ni++) {
                int row = wn * 32 + ni * 8 + grp;
                uint32_t base = sb + bufo + OFF_BH + row * 80 + h16 * 32 + tig * 4;
                bh[ni][0] = lds32(base);
                bh[ni][1] = lds32(base + 16);
                bl[ni][0] = lds32(base + (OFF_BL - OFF_BH));
                bl[ni][1] = lds32(base + (OFF_BL - OFF_BH) + 16);
            }
            #pragma unroll
            for (int mi = 0; mi < 2; mi++)
                #pragma unroll
                for (int ni = 0; ni < 4; ni++) {
                    float* a = acc[mi][ni];
                    mma16816h(a[0], a[1], a[2], a[3],
                              ah[mi][0], ah[mi][1], ah[mi][2], ah[mi][3],
                              bh[ni][0], bh[ni][1]);
                    mma16816h(a[0], a[1], a[2], a[3],
                              ah[mi][0], ah[mi][1], ah[mi][2], ah[mi][3],
                              bl[ni][0], bl[ni][1]);
                    if (THREE)
                        mma16816h(a[0], a[1], a[2], a[3],
                                  al[mi][0], al[mi][1], al[mi][2], al[mi][3],
                                  bh[ni][0], bh[ni][1]);
                }
        }
        __syncthreads();
    }

    #pragma unroll
    for (int ni = 0; ni < 4; ni++) {
        int gc = n0 + wn * 32 + ni * 8 + tig * 2;
        float bs0 = 0.f, bs1 = 0.f;
        if (bias1) { bs0 += bias1[gc]; bs1 += bias1[gc + 1]; }
        if (bias2) { bs0 += bias2[gc]; bs1 += bias2[gc + 1]; }
        #pragma unroll
        for (int mi = 0; mi < 2; mi++) {
            int gr = m0 + wm * 32 + mi * 16 + grp;
            float* a = acc[mi][ni];
            *(float2*)&C[(size_t)gr * N + gc] = make_float2(a[0] + bs0, a[1] + bs1);
            *(float2*)&C[(size_t)(gr + 8) * N + gc] = make_float2(a[2] + bs0, a[3] + bs1);
        }
    }
}

// ---------------- row softmax over 512 cols ---------------------------------
__global__ __launch_bounds__(256)
void softmax512(const float* __restrict__ logits, float* __restrict__ out)
{
    const int row = blockIdx.x;
    const int tid = threadIdx.x;
    const float* in = logits + (size_t)row * OO;
    float a = in[tid], b = in[tid + 256];

    float m = fmaxf(a, b);
    #pragma unroll
    for (int o = 16; o > 0; o >>= 1)
        m = fmaxf(m, __shfl_xor_sync(0xffffffffu, m, o));
    __shared__ float redm[8];
    __shared__ float reds[8];
    if ((tid & 31) == 0) redm[tid >> 5] = m;
    __syncthreads();
    float mm = redm[0];
    #pragma unroll
    for (int i = 1; i < 8; i++) mm = fmaxf(mm, redm[i]);

    float e0 = expf(a - mm), e1 = expf(b - mm);
    float s = e0 + e1;
    #pragma unroll
    for (int o = 16; o > 0; o >>= 1)
        s += __shfl_xor_sync(0xffffffffu, s, o);
    if ((tid & 31) == 0) reds[tid >> 5] = s;
    __syncthreads();
    float ss = 0.f;
    #pragma unroll
    for (int i = 0; i < 8; i++) ss += reds[i];
    float inv = 1.0f / ss;

    float* op = out + (size_t)row * OO;
    op[tid]       = e0 * inv;
    op[tid + 256] = e1 * inv;
}

// ---------------- launch -----------------------------------------------------
extern "C" void kernel_launch(void* const* d_in, const int* in_sizes, int n_in,
                              void* d_out, int out_size)
{
    const float* x     = (const float*)d_in[0];
    const float* h0    = (const float*)d_in[1];
    const float* W_ih  = (const float*)d_in[2];
    const float* W_hh  = (const float*)d_in[3];
    const float* b_ih  = (const float*)d_in[4];
    const float* b_hh  = (const float*)d_in[5];
    const float* W_out = (const float*)d_in[6];
    const float* b_out = (const float*)d_in[7];
    float* out = (float*)d_out;

    float *pre, *logits, *zfb;
    cudaGetSymbolAddress((void**)&pre,    g_pre);
    cudaGetSymbolAddress((void**)&logits, g_logits);
    cudaGetSymbolAddress((void**)&zfb,    g_zfallback);
    __half *xh, *xl, *wihh, *wihl, *wouth, *woutl, *zh16;
    cudaGetSymbolAddress((void**)&xh, g_xh);
    cudaGetSymbolAddress((void**)&xl, g_xl);
    cudaGetSymbolAddress((void**)&wihh, g_wihh);
    cudaGetSymbolAddress((void**)&wihl, g_wihl);
    cudaGetSymbolAddress((void**)&wouth, g_wouth);
    cudaGetSymbolAddress((void**)&woutl, g_woutl);
    cudaGetSymbolAddress((void**)&zh16, g_zh16);

    cudaFuncSetAttribute(hgemm<true>,  cudaFuncAttributeMaxDynamicSharedMemorySize, GSMEM);
    cudaFuncSetAttribute(hgemm<false>, cudaFuncAttributeMaxDynamicSharedMemorySize, GSMEM);
    cudaFuncSetAttribute(rnn_persistent, cudaFuncAttributeMaxDynamicSharedMemorySize, RNN_SMEM);

    float* z = (out_size >= (int)((size_t)MM * (OO + HH)))
                 ? out + (size_t)MM * OO : zfb;

    // 0) fused prep: fp16-pair splits of x/W_ih/W_out + h0 convert
    prep_all<<<592, 256>>>(x, W_ih, W_out, h0);

    // 1) pre = x @ W_ih^T + b_ih + b_hh   (3-term)
    dim3 g1(MM / 128, HH / 64);
    hgemm<true><<<g1, 256, GSMEM>>>(MM, HH, II, xh, xl, wihh, wihl, b_ih, b_hh, pre);

    // 2) recurrence (persistent, fp16 state, 2-store phase B)
    rnn_persistent<<<RNN_BLOCKS, 256, RNN_SMEM>>>(pre, W_hh, z);

    // 3) logits = z @ W_out^T + b_out   (2-term: zh only)
    dim3 g3(MM / 128, OO / 64);
    hgemm<false><<<g3, 256, GSMEM>>>(MM, OO, HH, zh16, nullptr, wouth, woutl, b_out, nullptr, logits);

    // 4) softmax rows -> out
    softmax512<<<MM, 256>>>(logits, out);
}

// round 17
// speedup vs baseline: 1.1785x; 1.0953x over previous
#include <cuda_runtime.h>
#include <cuda_bf16.h>
#include <cuda_fp16.h>
#include <cstdint>

// Problem dims
#define BB   32
#define TT   512
#define II   512
#define HH   1024
#define OO   512
#define MM   (BB*TT)

#define RNN_BLOCKS 64

// ---------------- scratch (static device globals) ---------------------------
__device__ float g_pre[MM * HH];
__device__ float g_logits[MM * OO];
__device__ float g_zfallback[MM * HH];

__device__ __half g_xh[MM * II];
__device__ __half g_wihh[HH * II],  g_wihl[HH * II];
__device__ __half g_wouth[OO * HH];
__device__ __half g_zh16[MM * HH];
__device__ __half g_h0h16[BB * HH];

// per-(block, mw-half) spread flags (128B apart)
__device__ unsigned g_flags[RNN_BLOCKS * 2 * 32];

// ---------------- helpers ----------------------------------------------------
__device__ __forceinline__ void mma16816h(float& d0, float& d1, float& d2, float& d3,
                                          uint32_t a0, uint32_t a1, uint32_t a2, uint32_t a3,
                                          uint32_t b0, uint32_t b1)
{
    asm volatile(
        "mma.sync.aligned.m16n8k16.row.col.f32.f16.f16.f32 "
        "{%0,%1,%2,%3},{%4,%5,%6,%7},{%8,%9},{%0,%1,%2,%3};"
        : "+f"(d0), "+f"(d1), "+f"(d2), "+f"(d3)
        : "r"(a0), "r"(a1), "r"(a2), "r"(a3), "r"(b0), "r"(b1));
}

__device__ __forceinline__ void ldsm4(uint32_t& r0, uint32_t& r1, uint32_t& r2, uint32_t& r3,
                                      uint32_t addr)
{
    asm volatile("ldmatrix.sync.aligned.m8n8.x4.shared.b16 {%0,%1,%2,%3}, [%4];"
                 : "=r"(r0), "=r"(r1), "=r"(r2), "=r"(r3) : "r"(addr));
}

__device__ __forceinline__ uint32_t lds32(uint32_t a) {
    uint32_t v;
    asm volatile("ld.shared.b32 %0, [%1];" : "=r"(v) : "r"(a));
    return v;
}

__device__ __forceinline__ void cpa16(uint32_t s, const void* g) {
    asm volatile("cp.async.cg.shared.global [%0], [%1], 16;" :: "r"(s), "l"(g));
}

__device__ __forceinline__ uint32_t pack_h2(float x, float y) {
    __half2 t = __floats2half2_rn(x, y);
    return *reinterpret_cast<uint32_t*>(&t);
}

__device__ __forceinline__ void flag_store(unsigned* p, unsigned v) {
    asm volatile("st.release.gpu.u32 [%0], %1;" :: "l"(p), "r"(v));
}
__device__ __forceinline__ void flag_wait(const unsigned* p, unsigned target) {
    unsigned v;
    do {
        asm volatile("ld.acquire.gpu.u32 %0, [%1];" : "=r"(v) : "l"(p));
    } while ((int)(v - target) < 0);
}

__device__ __forceinline__ void nbar_sync(int id, int cnt) {
    asm volatile("bar.sync %0, %1;" :: "r"(id), "r"(cnt) : "memory");
}
__device__ __forceinline__ void nbar_arrive(int id, int cnt) {
    asm volatile("bar.arrive %0, %1;" :: "r"(id), "r"(cnt) : "memory");
}

// ---------------- persistent Elman recurrence (fp16 state, dataflow) ---------
#define WBUF   8448                    // per-warp fp16 slice
#define SM_PS  (8 * WBUF)              // 67584
#define PSROW  18
#define PS_KW  (16 * PSROW)
#define PS_HALF (4 * PS_KW)
#define RNN_SMEM (SM_PS + 2 * 2 * PS_HALF * 4)

__global__ __launch_bounds__(256, 1)
void rnn_persistent(const float* __restrict__ pre,
                    const float* __restrict__ W_hh,
                    float* __restrict__ z_out)
{
    extern __shared__ __align__(16) char dsm[];
    const uint32_t sb = (uint32_t)__cvta_generic_to_shared(dsm);

    const int tid  = threadIdx.x;
    const int wid  = tid >> 5;
    const int lane = tid & 31;
    const int grp  = lane >> 2;       // 0..7
    const int tig  = lane & 3;        // 0..3
    const int jc   = blockIdx.x;      // 0..63
    const int kw   = wid & 3;         // k chunk of 256
    const int mw   = wid >> 2;        // b half

    // replay-safe base (all flags equal at launch start)
    const unsigned base = g_flags[blockIdx.x * 64];

    // ---- preload W fragments (fp16) into registers, whole run ----
    uint32_t w0[2][16], w1[2][16];
    #pragma unroll
    for (int nt = 0; nt < 2; nt++) {
        const int jrow = jc * 16 + nt * 8 + grp;
        const float* Wr = W_hh + (size_t)jrow * HH + kw * 256;
        #pragma unroll
        for (int ki = 0; ki < 16; ki++) {
            int k0 = ki * 16 + tig * 2;
            w0[nt][ki] = pack_h2(Wr[k0],     Wr[k0 + 1]);
            w1[nt][ki] = pack_h2(Wr[k0 + 8], Wr[k0 + 9]);
        }
    }

    // warp-private staging buffer
    const uint32_t wb = sb + (uint32_t)wid * WBUF;
    const uint32_t lrow = (lane & 7) + ((lane >> 3) & 1) * 8;
    const uint32_t aoff = lrow * 528 + ((uint32_t)lane >> 4) * 16;

    // producer half-flag this lane polls: 16 producers cover k in [kw*256,+256)
    const int pflag = ((kw * 16 + (lane & 15)) * 2 + mw) * 32;

    // phase-B mapping within the 128-thread half
    const int ltid = tid & 127;
    const int lb   = ltid >> 3;               // local b 0..15
    const int pbB  = mw * 16 + lb;            // global b
    const int pbJ  = (ltid & 7) * 2;          // j pair within chunk

    float* const psum = (float*)(dsm + SM_PS);   // [parity][mw][kw][16][PSROW]

    const int barA = 1 + mw;   // psum-ready
    const int barB = 3 + mw;   // z-done

    for (int t = 0; t < TT; t++) {
        // prefetch pre (phase-B input, independent of h)
        float2 pre2 = *(const float2*)&pre[((size_t)pbB * TT + t) * HH + jc * 16 + pbJ];

        // ---- dataflow wait: this warp's 16 producer half-flags ----
        if (t > 0)
            flag_wait(&g_flags[pflag], base + (unsigned)t);
        __syncwarp();

        // ---- stage own 16-row x 256-k fp16 slice, TWO k-half groups ----
        {
            const __half* sh;
            size_t rstride, off0;
            if (t == 0) {
                sh = g_h0h16;
                rstride = HH;
                off0 = (size_t)(mw * 16) * HH + kw * 256;
            } else {
                sh = g_zh16;
                rstride = (size_t)TT * HH;
                off0 = ((size_t)(mw * 16) * TT + (t - 1)) * HH + kw * 256;
            }
            // group 1: cols 0..15 (k 0..127)
            #pragma unroll
            for (int p = 0; p < 8; p++) {
                int chunk = lane + p * 32;      // 0..255
                int row   = chunk >> 4;         // 0..15
                int c     = chunk & 15;         // 0..15
                cpa16(wb + row * 528 + c * 16, sh + off0 + (size_t)row * rstride + c * 8);
            }
            asm volatile("cp.async.commit_group;" ::: "memory");
            // group 2: cols 16..31 (k 128..255)
            #pragma unroll
            for (int p = 0; p < 8; p++) {
                int chunk = lane + p * 32;
                int row   = chunk >> 4;
                int c     = (chunk & 15) + 16;
                cpa16(wb + row * 528 + c * 16, sh + off0 + (size_t)row * rstride + c * 8);
            }
            asm volatile("cp.async.commit_group;" ::: "memory");
        }

        float a1[2][4] = {{0,0,0,0},{0,0,0,0}};

        // first k-half resident; second still in flight
        asm volatile("cp.async.wait_group 1;" ::: "memory");
        __syncwarp();
        #pragma unroll
        for (int ki = 0; ki < 8; ki++) {
            uint32_t h0r, h1r, h2r, h3r;
            ldsm4(h0r, h1r, h2r, h3r, wb + aoff + ki * 32);
            #pragma unroll
            for (int nt = 0; nt < 2; nt++) {
                mma16816h(a1[nt][0], a1[nt][1], a1[nt][2], a1[nt][3],
                          h0r, h1r, h2r, h3r, w0[nt][ki], w1[nt][ki]);
            }
        }
        asm volatile("cp.async.wait_group 0;" ::: "memory");
        __syncwarp();
        #pragma unroll
        for (int ki = 8; ki < 16; ki++) {
            uint32_t h0r, h1r, h2r, h3r;
            ldsm4(h0r, h1r, h2r, h3r, wb + aoff + ki * 32);
            #pragma unroll
            for (int nt = 0; nt < 2; nt++) {
                mma16816h(a1[nt][0], a1[nt][1], a1[nt][2], a1[nt][3],
                          h0r, h1r, h2r, h3r, w0[nt][ki], w1[nt][ki]);
            }
        }

        // ---- per-warp k-partials to SMEM (parity double-buffered) ----
        {
            float* pb = psum + ((t & 1) * 2 + mw) * PS_HALF + kw * PS_KW;
            #pragma unroll
            for (int nt = 0; nt < 2; nt++) {
                int jj = nt * 8 + tig * 2;
                float* p = pb + grp * PSROW + jj;
                *(float2*)p               = make_float2(a1[nt][0], a1[nt][1]);
                *(float2*)(p + 8 * PSROW) = make_float2(a1[nt][2], a1[nt][3]);
            }
        }
        nbar_sync(barA, 128);   // psum ready within this half

        // ---- phase B: reduce 4 kw, tanh, store zh16 (flag-guarded) ----
        float h0v, h1v;
        size_t zidx;
        {
            const float* pb = psum + ((t & 1) * 2 + mw) * PS_HALF;
            float s0 = pre2.x, s1 = pre2.y;
            #pragma unroll
            for (int kk = 0; kk < 4; kk++) {
                float2 p = *(float2*)&pb[kk * PS_KW + lb * PSROW + pbJ];
                s0 += p.x; s1 += p.y;
            }
            h0v = tanhf(s0);
            h1v = tanhf(s1);
            zidx = ((size_t)pbB * TT + t) * HH + jc * 16 + pbJ;
            *(uint32_t*)&g_zh16[zidx] = pack_h2(h0v, h1v);
        }

        // ---- z-done: kw=0 warp syncs + publishes; others arrive & fly ----
        if (kw == 0) {
            nbar_sync(barB, 128);
            if (lane == 0)
                flag_store(&g_flags[(blockIdx.x * 2 + mw) * 32], base + (unsigned)t + 1u);
        } else {
            nbar_arrive(barB, 128);
        }

        // z fp32 output store AFTER the flag (off the critical chain)
        *(float2*)&z_out[zidx] = make_float2(h0v, h1v);
    }
}

// ---------------- fused prep: fp16 converts (x, W_ih hi/lo, W_out, h0) -------
#define N_X   (MM * II)
#define N_WI  (HH * II)
#define N_WO  (OO * HH)
#define N_H0  (BB * HH)
#define N_PREP (N_X + N_WI + N_WO + N_H0)

__global__ __launch_bounds__(256)
void prep_all(const float* __restrict__ x, const float* __restrict__ W_ih,
              const float* __restrict__ W_out, const float* __restrict__ h0)
{
    int stride = gridDim.x * 256;
    for (int i = blockIdx.x * 256 + threadIdx.x; i < N_PREP; i += stride) {
        int idx = i;
        if (idx < N_X) {
            g_xh[idx] = __float2half_rn(x[idx]);
        } else if ((idx -= N_X) < N_WI) {
            float v = W_ih[idx];
            __half h = __float2half_rn(v);
            g_wihh[idx] = h;
            g_wihl[idx] = __float2half_rn(v - __half2float(h));
        } else if ((idx -= N_WI) < N_WO) {
            g_wouth[idx] = __float2half_rn(W_out[idx]);
        } else {
            idx -= N_WO;
            g_h0h16[idx] = __float2half_rn(h0[idx]);
        }
    }
}

// ---------------- mma.sync fp16 GEMM, 128x64 tile ----------------------------
// TERMS=2: C = A*Bh + A*Bl ;  TERMS=1: C = A*Bh
#define GA_BYTES  (128 * 80)
#define GB_BYTES  (64 * 80)
#define OFF_BH    GA_BYTES
#define OFF_BL    (GA_BYTES + GB_BYTES)
#define GBUF      (GA_BYTES + 2 * GB_BYTES)   // 20480
#define GSMEM     (2 * GBUF)                  // 40960

template <int TERMS>
__global__ __launch_bounds__(256)
void hgemm(int M, int N, int K,
           const __half* __restrict__ A,
           const __half* __restrict__ Bh, const __half* __restrict__ Bl,
           const float* __restrict__ bias1, const float* __restrict__ bias2,
           float* __restrict__ C)
{
    extern __shared__ __align__(16) char dsm[];
    const uint32_t sb = (uint32_t)__cvta_generic_to_shared(dsm);

    const int tid  = threadIdx.x;
    const int wid  = tid >> 5;
    const int lane = tid & 31;
    const int grp  = lane >> 2;
    const int tig  = lane & 3;
    const int wm   = wid >> 1;      // 0..3 : 32-row slice
    const int wn   = wid & 1;       // 0..1 : 32-col slice
    const int m0   = blockIdx.x * 128;
    const int n0   = blockIdx.y * 64;

    float acc[2][4][4];
    #pragma unroll
    for (int i = 0; i < 2; i++)
        #pragma unroll
        for (int j = 0; j < 4; j++)
            #pragma unroll
            for (int q = 0; q < 4; q++) acc[i][j][q] = 0.f;

    const int lrowB = tid >> 2;          // 0..63
    const int lcB   = tid & 3;

    auto issue = [&](int kt, int buf) {
        #pragma unroll
        for (int r = 0; r < 2; r++) {
            int idx = tid + r * 256;
            int row = idx >> 2;
            int c16 = idx & 3;
            uint32_t so = (uint32_t)buf * GBUF + row * 80 + c16 * 16;
            size_t go  = (size_t)(m0 + row) * K + kt * 32 + c16 * 8;
            cpa16(sb + so, A + go);
        }
        {
            uint32_t so = (uint32_t)buf * GBUF + lrowB * 80 + lcB * 16;
            size_t go  = (size_t)(n0 + lrowB) * K + kt * 32 + lcB * 8;
            cpa16(sb + so + OFF_BH, Bh + go);
            if (TERMS == 2)
                cpa16(sb + so + OFF_BL, Bl + go);
        }
        asm volatile("cp.async.commit_group;" ::: "memory");
    };

    const int KT = K >> 5;
    issue(0, 0);

    for (int kt = 0; kt < KT; kt++) {
        if (kt + 1 < KT) {
            issue(kt + 1, (kt + 1) & 1);
            asm volatile("cp.async.wait_group 1;" ::: "memory");
        } else {
            asm volatile("cp.async.wait_group 0;" ::: "memory");
        }
        __syncthreads();

        const uint32_t bufo = (uint32_t)(kt & 1) * GBUF;
        #pragma unroll
        for (int h16 = 0; h16 < 2; h16++) {
            uint32_t ah[2][4];
            #pragma unroll
            for (int mi = 0; mi < 2; mi++) {
                int row = wm * 32 + mi * 16 + grp;
                uint32_t base = sb + bufo + row * 80 + h16 * 32 + tig * 4;
                ah[mi][0] = lds32(base);
                ah[mi][1] = lds32(base + 8 * 80);
                ah[mi][2] = lds32(base + 16);
                ah[mi][3] = lds32(base + 8 * 80 + 16);
            }
            uint32_t bh[4][2], bl[4][2];
            #pragma unroll
            for (int ni = 0; ni < 4; ni++) {
                int row = wn * 32 + ni * 8 + grp;
                uint32_t base = sb + bufo + OFF_BH + row * 80 + h16 * 32 + tig * 4;
                bh[ni][0] = lds32(base);
                bh[ni][1] = lds32(base + 16);
                if (TERMS == 2) {
                    bl[ni][0] = lds32(base + GB_BYTES);
                    bl[ni][1] = lds32(base + GB_BYTES + 16);
                }
            }
            #pragma unroll
            for (int mi = 0; mi < 2; mi++)
                #pragma unroll
                for (int ni = 0; ni < 4; ni++) {
                    float* a = acc[mi][ni];
                    mma16816h(a[0], a[1], a[2], a[3],
                              ah[mi][0], ah[mi][1], ah[mi][2], ah[mi][3],
                              bh[ni][0], bh[ni][1]);
                    if (TERMS == 2)
                        mma16816h(a[0], a[1], a[2], a[3],
                                  ah[mi][0], ah[mi][1], ah[mi][2], ah[mi][3],
                                  bl[ni][0], bl[ni][1]);
                }
        }
        __syncthreads();
    }

    #pragma unroll
    for (int ni = 0; ni < 4; ni++) {
        int gc = n0 + wn * 32 + ni * 8 + tig * 2;
        float bs0 = 0.f, bs1 = 0.f;
        if (bias1) { bs0 += bias1[gc]; bs1 += bias1[gc + 1]; }
        if (bias2) { bs0 += bias2[gc]; bs1 += bias2[gc + 1]; }
        #pragma unroll
        for (int mi = 0; mi < 2; mi++) {
            int gr = m0 + wm * 32 + mi * 16 + grp;
            float* a = acc[mi][ni];
            *(float2*)&C[(size_t)gr * N + gc] = make_float2(a[0] + bs0, a[1] + bs1);
            *(float2*)&C[(size_t)(gr + 8) * N + gc] = make_float2(a[2] + bs0, a[3] + bs1);
        }
    }
}

// ---------------- row softmax over 512 cols ---------------------------------
__global__ __launch_bounds__(256)
void softmax512(const float* __restrict__ logits, float* __restrict__ out)
{
    const int row = blockIdx.x;
    const int tid = threadIdx.x;
    const float* in = logits + (size_t)row * OO;
    float a = in[tid], b = in[tid + 256];

    float m = fmaxf(a, b);
    #pragma unroll
    for (int o = 16; o > 0; o >>= 1)
        m = fmaxf(m, __shfl_xor_sync(0xffffffffu, m, o));
    __shared__ float redm[8];
    __shared__ float reds[8];
    if ((tid & 31) == 0) redm[tid >> 5] = m;
    __syncthreads();
    float mm = redm[0];
    #pragma unroll
    for (int i = 1; i < 8; i++) mm = fmaxf(mm, redm[i]);

    float e0 = expf(a - mm), e1 = expf(b - mm);
    float s = e0 + e1;
    #pragma unroll
    for (int o = 16; o > 0; o >>= 1)
        s += __shfl_xor_sync(0xffffffffu, s, o);
    if ((tid & 31) == 0) reds[tid >> 5] = s;
    __syncthreads();
    float ss = 0.f;
    #pragma unroll
    for (int i = 0; i < 8; i++) ss += reds[i];
    float inv = 1.0f / ss;

    float* op = out + (size_t)row * OO;
    op[tid]       = e0 * inv;
    op[tid + 256] = e1 * inv;
}

// ---------------- launch -----------------------------------------------------
extern "C" void kernel_launch(void* const* d_in, const int* in_sizes, int n_in,
                              void* d_out, int out_size)
{
    const float* x     = (const float*)d_in[0];
    const float* h0    = (const float*)d_in[1];
    const float* W_ih  = (const float*)d_in[2];
    const float* W_hh  = (const float*)d_in[3];
    const float* b_ih  = (const float*)d_in[4];
    const float* b_hh  = (const float*)d_in[5];
    const float* W_out = (const float*)d_in[6];
    const float* b_out = (const float*)d_in[7];
    float* out = (float*)d_out;

    float *pre, *logits, *zfb;
    cudaGetSymbolAddress((void**)&pre,    g_pre);
    cudaGetSymbolAddress((void**)&logits, g_logits);
    cudaGetSymbolAddress((void**)&zfb,    g_zfallback);
    __half *xh, *wihh, *wihl, *wouth, *zh16;
    cudaGetSymbolAddress((void**)&xh, g_xh);
    cudaGetSymbolAddress((void**)&wihh, g_wihh);
    cudaGetSymbolAddress((void**)&wihl, g_wihl);
    cudaGetSymbolAddress((void**)&wouth, g_wouth);
    cudaGetSymbolAddress((void**)&zh16, g_zh16);

    cudaFuncSetAttribute(hgemm<2>, cudaFuncAttributeMaxDynamicSharedMemorySize, GSMEM);
    cudaFuncSetAttribute(hgemm<1>, cudaFuncAttributeMaxDynamicSharedMemorySize, GSMEM);
    cudaFuncSetAttribute(rnn_persistent, cudaFuncAttributeMaxDynamicSharedMemorySize, RNN_SMEM);

    float* z = (out_size >= (int)((size_t)MM * (OO + HH)))
                 ? out + (size_t)MM * OO : zfb;

    // 0) fused prep: fp16 converts (x hi; W_ih hi+lo; W_out hi; h0)
    prep_all<<<592, 256>>>(x, W_ih, W_out, h0);

    // 1) pre = x @ W_ih^T + b_ih + b_hh   (2-term: xh * (Wh + Wl))
    dim3 g1(MM / 128, HH / 64);
    hgemm<2><<<g1, 256, GSMEM>>>(MM, HH, II, xh, wihh, wihl, b_ih, b_hh, pre);

    // 2) recurrence (persistent, fp16 state, split-stage, post-flag z store)
    rnn_persistent<<<RNN_BLOCKS, 256, RNN_SMEM>>>(pre, W_hh, z);

    // 3) logits = z @ W_out^T + b_out   (1-term: zh * Wh)
    dim3 g3(MM / 128, OO / 64);
    hgemm<1><<<g3, 256, GSMEM>>>(MM, OO, HH, zh16, wouth, nullptr, b_out, nullptr, logits);

    // 4) softmax rows -> out
    softmax512<<<MM, 256>>>(logits, out);
}